// round 10
// baseline (speedup 1.0000x reference)
#include <cuda_runtime.h>
#include <cuda_bf16.h>
#include <cstdint>

#define TILE 256
#define STAGES 3
#define NTHREADS 256
#define NBLOCKS 2368

// Per-block partials: every slot written each run -> no init kernel needed.
__device__ float g_p_iou[NBLOCKS];
__device__ float g_p_mse[NBLOCKS];
__device__ unsigned int g_p_ni[NBLOCKS];
// Ticket counter: statically 0; last block resets it -> graph-replay safe.
__device__ unsigned int g_ticket = 0;

__device__ __forceinline__ uint32_t smem_u32(const void* p) {
    uint32_t a;
    asm("{ .reg .u64 t; cvta.to.shared.u64 t, %1; cvt.u32.u64 %0, t; }" : "=r"(a) : "l"(p));
    return a;
}

__device__ __forceinline__ void mbar_init(uint32_t mbar, uint32_t count) {
    asm volatile("mbarrier.init.shared.b64 [%0], %1;" :: "r"(mbar), "r"(count) : "memory");
}

__device__ __forceinline__ void mbar_expect_tx(uint32_t mbar, uint32_t bytes) {
    asm volatile("mbarrier.arrive.expect_tx.shared.b64 _, [%0], %1;" :: "r"(mbar), "r"(bytes) : "memory");
}

__device__ __forceinline__ void bulk_ld(uint32_t dst, const void* src, uint32_t bytes, uint32_t mbar) {
    asm volatile(
        "cp.async.bulk.shared::cta.global.mbarrier::complete_tx::bytes [%0], [%1], %2, [%3];"
        :: "r"(dst), "l"(src), "r"(bytes), "r"(mbar) : "memory");
}

__device__ __forceinline__ void mbar_wait(uint32_t mbar, uint32_t parity) {
    asm volatile(
        "{\n\t"
        ".reg .pred P;\n\t"
        "WAIT_%=:\n\t"
        "mbarrier.try_wait.parity.acquire.cta.shared::cta.b64 P, [%0], %1, 0x989680;\n\t"
        "@P bra DONE_%=;\n\t"
        "bra WAIT_%=;\n\t"
        "DONE_%=:\n\t"
        "}"
        :: "r"(mbar), "r"(parity) : "memory");
}

__device__ __forceinline__ void process_box(const float4 p, const float4 g,
                                            float& iou_sum, float& mse_sum,
                                            unsigned int& n_inc) {
    const float x_min_t = g.x - g.z * 0.5f;
    const float x_max_t = g.x + g.z * 0.5f;
    const float y_min_t = g.y - g.w * 0.5f;
    const float y_max_t = g.y + g.w * 0.5f;
    const float x_min_p = fmaxf(p.x - p.z * 0.5f, 0.0f);
    const float x_max_p = fminf(p.x + p.z * 0.5f, 1.0f);
    const float y_min_p = fmaxf(p.y - p.w * 0.5f, 0.0f);
    const float y_max_p = fminf(p.y + p.w * 0.5f, 1.0f);
    const float o0 = fmaxf(x_min_t, x_min_p);
    const float o1 = fmaxf(y_min_t, y_min_p);
    const float o2 = fminf(x_max_t, x_max_p);
    const float o3 = fminf(y_max_t, y_max_p);

    const bool inc = (o2 < o0) || (o3 < o1);

    const float dx = p.x - g.x;
    const float dy = p.y - g.y;
    const float dz = p.z - g.z;
    const float dw = p.w - g.w;
    const float sq = dx * dx + dy * dy + dz * dz + dw * dw;

    const float inter = (o2 - o0) * (o3 - o1);
    const float area_p = p.z * p.w;
    const float area_g = g.z * g.w;
    const float iou = __fdividef(inter, area_p + area_g - inter + 1e-7f);

    mse_sum += inc ? sq : 0.0f;
    iou_sum += inc ? 0.0f : iou;
    n_inc += inc ? 1u : 0u;
}

__global__ void __launch_bounds__(NTHREADS) iou_dots_tma(
    const float4* __restrict__ pr,
    const float4* __restrict__ gt,
    float* __restrict__ out,
    int n)
{
    __shared__ alignas(128) float4 s_pr[STAGES][TILE];
    __shared__ alignas(128) float4 s_gt[STAGES][TILE];
    __shared__ alignas(8) unsigned long long s_mbar[STAGES];

    const int tid = threadIdx.x;
    const int n_tiles = (n + TILE - 1) / TILE;

    const uint32_t mbar0 = smem_u32(&s_mbar[0]);
    const uint32_t spr0 = smem_u32(&s_pr[0][0]);
    const uint32_t sgt0 = smem_u32(&s_gt[0][0]);

    if (tid == 0) {
        #pragma unroll
        for (int s = 0; s < STAGES; s++) mbar_init(mbar0 + s * 8, 1u);
        asm volatile("fence.proxy.async.shared::cta;" ::: "memory");
    }
    __syncthreads();

    // Prime the pipeline.
    if (tid == 0) {
        #pragma unroll
        for (int s = 0; s < STAGES; s++) {
            const int t = blockIdx.x + s * gridDim.x;
            if (t < n_tiles) {
                const int base = t * TILE;
                const uint32_t bytes = (uint32_t)min(TILE, n - base) * 16u;
                mbar_expect_tx(mbar0 + s * 8, 2u * bytes);
                bulk_ld(spr0 + s * (TILE * 16), pr + base, bytes, mbar0 + s * 8);
                bulk_ld(sgt0 + s * (TILE * 16), gt + base, bytes, mbar0 + s * 8);
            }
        }
    }

    float iou_sum = 0.0f;
    float mse_sum = 0.0f;
    unsigned int n_inc = 0u;

    int slot = 0;
    uint32_t parity = 0u;
    for (int k = 0;; k++) {
        const int t = blockIdx.x + k * gridDim.x;
        if (t >= n_tiles) break;

        mbar_wait(mbar0 + slot * 8, parity);

        const int base = t * TILE;
        const int boxes = min(TILE, n - base);
        if (tid < boxes) {
            const float4 p = s_pr[slot][tid];
            const float4 g = s_gt[slot][tid];
            process_box(p, g, iou_sum, mse_sum, n_inc);
        }
        __syncthreads();  // all readers done with this slot

        if (tid == 0) {
            const int tn = blockIdx.x + (k + STAGES) * gridDim.x;
            if (tn < n_tiles) {
                const int nb = tn * TILE;
                const uint32_t bytes = (uint32_t)min(TILE, n - nb) * 16u;
                mbar_expect_tx(mbar0 + slot * 8, 2u * bytes);
                bulk_ld(spr0 + slot * (TILE * 16), pr + nb, bytes, mbar0 + slot * 8);
                bulk_ld(sgt0 + slot * (TILE * 16), gt + nb, bytes, mbar0 + slot * 8);
            }
        }

        if (++slot == STAGES) { slot = 0; parity ^= 1u; }
    }

    // intra-warp reduce
    #pragma unroll
    for (int off = 16; off > 0; off >>= 1) {
        iou_sum += __shfl_down_sync(0xFFFFFFFFu, iou_sum, off);
        mse_sum += __shfl_down_sync(0xFFFFFFFFu, mse_sum, off);
        n_inc   += __shfl_down_sync(0xFFFFFFFFu, n_inc, off);
    }

    __shared__ float s_iou[8];
    __shared__ float s_mse[8];
    __shared__ unsigned int s_ni[8];
    __shared__ bool s_last;
    const int wid = tid >> 5;
    const int lid = tid & 31;
    if (lid == 0) {
        s_iou[wid] = iou_sum;
        s_mse[wid] = mse_sum;
        s_ni[wid] = n_inc;
    }
    __syncthreads();
    if (tid == 0) {
        float biou = 0.0f, bmse = 0.0f;
        unsigned int bni = 0u;
        #pragma unroll
        for (int w = 0; w < NTHREADS / 32; w++) {
            biou += s_iou[w];
            bmse += s_mse[w];
            bni += s_ni[w];
        }
        g_p_iou[blockIdx.x] = biou;
        g_p_mse[blockIdx.x] = bmse;
        g_p_ni[blockIdx.x] = bni;
        __threadfence();
        const unsigned int old = atomicAdd(&g_ticket, 1u);
        s_last = (old == gridDim.x - 1u);
    }
    __syncthreads();

    if (s_last) {
        double diou = 0.0, dmse = 0.0;
        unsigned long long dni = 0ull;
        for (int b = tid; b < (int)gridDim.x; b += NTHREADS) {
            diou += (double)g_p_iou[b];
            dmse += (double)g_p_mse[b];
            dni += (unsigned long long)g_p_ni[b];
        }
        #pragma unroll
        for (int off = 16; off > 0; off >>= 1) {
            diou += __shfl_down_sync(0xFFFFFFFFu, diou, off);
            dmse += __shfl_down_sync(0xFFFFFFFFu, dmse, off);
            dni  += __shfl_down_sync(0xFFFFFFFFu, dni, off);
        }
        __shared__ double f_iou[8];
        __shared__ double f_mse[8];
        __shared__ unsigned long long f_ni[8];
        if (lid == 0) {
            f_iou[wid] = diou;
            f_mse[wid] = dmse;
            f_ni[wid] = dni;
        }
        __syncthreads();
        if (tid == 0) {
            double tiou = 0.0, tmse = 0.0;
            unsigned long long tni = 0ull;
            #pragma unroll
            for (int w = 0; w < NTHREADS / 32; w++) {
                tiou += f_iou[w];
                tmse += f_mse[w];
                tni += f_ni[w];
            }
            const unsigned long long tnc = (unsigned long long)n - tni;
            const double mse_denom = (double)((tni > 0ull) ? tni * 4ull : 1ull);
            const double iou_denom = (double)((tnc > 0ull) ? tnc : 1ull);
            const float mse_mean = (float)(tmse / mse_denom);
            const float iou_mean = (float)(tiou / iou_denom);
            float res_full = iou_mean + ((tni > 0ull) ? -mse_mean : 0.0f);
            out[0] = (tnc > 0ull) ? res_full : -mse_mean;
            g_ticket = 0u;  // reset for next graph replay
        }
    }
}

extern "C" void kernel_launch(void* const* d_in, const int* in_sizes, int n_in,
                              void* d_out, int out_size) {
    const float4* pr = (const float4*)d_in[0];
    const float4* gt = (const float4*)d_in[1];
    float* out = (float*)d_out;
    const int n = in_sizes[0] / 4;

    iou_dots_tma<<<NBLOCKS, NTHREADS>>>(pr, gt, out, n);
}

// round 11
// speedup vs baseline: 1.0505x; 1.0505x over previous
#include <cuda_runtime.h>
#include <cuda_bf16.h>

#define NTHREADS 1024
#define NBLOCKS 296   // 148 SMs x 2 CTAs -> single wave, oe=2

// Per-block partials: every slot written each run -> no init kernel needed.
__device__ float g_p_iou[NBLOCKS];
__device__ float g_p_mse[NBLOCKS];
__device__ unsigned int g_p_ni[NBLOCKS];
// Ticket counter: statically 0; last block resets it -> graph-replay safe.
__device__ unsigned int g_ticket = 0;

__device__ __forceinline__ void process_box(const float4 p, const float4 g,
                                            float& iou_sum, float& mse_sum,
                                            unsigned int& n_inc) {
    // gt corners (cx,cy,w,h -> xyxy)
    const float x_min_t = g.x - g.z * 0.5f;
    const float x_max_t = g.x + g.z * 0.5f;
    const float y_min_t = g.y - g.w * 0.5f;
    const float y_max_t = g.y + g.w * 0.5f;
    // pred corners clipped to [0,1]
    const float x_min_p = fmaxf(p.x - p.z * 0.5f, 0.0f);
    const float x_max_p = fminf(p.x + p.z * 0.5f, 1.0f);
    const float y_min_p = fmaxf(p.y - p.w * 0.5f, 0.0f);
    const float y_max_p = fminf(p.y + p.w * 0.5f, 1.0f);
    // overlap box
    const float o0 = fmaxf(x_min_t, x_min_p);
    const float o1 = fmaxf(y_min_t, y_min_p);
    const float o2 = fminf(x_max_t, x_max_p);
    const float o3 = fminf(y_max_t, y_max_p);

    const bool inc = (o2 < o0) || (o3 < o1);

    // Branchless: compute both contributions, select.
    const float dx = p.x - g.x;
    const float dy = p.y - g.y;
    const float dz = p.z - g.z;
    const float dw = p.w - g.w;
    const float sq = dx * dx + dy * dy + dz * dz + dw * dw;

    const float inter = (o2 - o0) * (o3 - o1);
    const float area_p = p.z * p.w;
    const float area_g = g.z * g.w;
    const float iou = __fdividef(inter, area_p + area_g - inter + 1e-7f);

    mse_sum += inc ? sq : 0.0f;
    iou_sum += inc ? 0.0f : iou;
    n_inc += inc ? 1u : 0u;
}

__global__ void __launch_bounds__(NTHREADS) iou_dots_fused(
    const float4* __restrict__ pr,
    const float4* __restrict__ gt,
    float* __restrict__ out,
    int n)
{
    float iou_sum = 0.0f;
    float mse_sum = 0.0f;
    unsigned int n_inc = 0u;

    const int stride = gridDim.x * blockDim.x;
    int i = blockIdx.x * blockDim.x + threadIdx.x;

    // x2 unroll: 4 independent LDG.128 in flight before any compute.
    for (; i + stride < n; i += 2 * stride) {
        const float4 p0 = pr[i];
        const float4 g0 = gt[i];
        const float4 p1 = pr[i + stride];
        const float4 g1 = gt[i + stride];
        process_box(p0, g0, iou_sum, mse_sum, n_inc);
        process_box(p1, g1, iou_sum, mse_sum, n_inc);
    }
    if (i < n) {
        process_box(pr[i], gt[i], iou_sum, mse_sum, n_inc);
    }

    // intra-warp reduce
    #pragma unroll
    for (int off = 16; off > 0; off >>= 1) {
        iou_sum += __shfl_down_sync(0xFFFFFFFFu, iou_sum, off);
        mse_sum += __shfl_down_sync(0xFFFFFFFFu, mse_sum, off);
        n_inc   += __shfl_down_sync(0xFFFFFFFFu, n_inc, off);
    }

    __shared__ float s_iou[32];
    __shared__ float s_mse[32];
    __shared__ unsigned int s_ni[32];
    __shared__ bool s_last;
    const int wid = threadIdx.x >> 5;
    const int lid = threadIdx.x & 31;
    if (lid == 0) {
        s_iou[wid] = iou_sum;
        s_mse[wid] = mse_sum;
        s_ni[wid] = n_inc;
    }
    __syncthreads();
    if (wid == 0) {
        float biou = s_iou[lid];
        float bmse = s_mse[lid];
        unsigned int bni = s_ni[lid];
        #pragma unroll
        for (int off = 16; off > 0; off >>= 1) {
            biou += __shfl_down_sync(0xFFFFFFFFu, biou, off);
            bmse += __shfl_down_sync(0xFFFFFFFFu, bmse, off);
            bni  += __shfl_down_sync(0xFFFFFFFFu, bni, off);
        }
        if (lid == 0) {
            g_p_iou[blockIdx.x] = biou;
            g_p_mse[blockIdx.x] = bmse;
            g_p_ni[blockIdx.x] = bni;
            __threadfence();
            const unsigned int old = atomicAdd(&g_ticket, 1u);
            s_last = (old == gridDim.x - 1u);
        }
    }
    __syncthreads();

    if (s_last) {
        // Last block reduces all per-block partials and finalizes.
        // Only 296 entries -> one warp-stride pass for first 256 threads.
        double diou = 0.0, dmse = 0.0;
        unsigned long long dni = 0ull;
        for (int b = threadIdx.x; b < (int)gridDim.x; b += NTHREADS) {
            diou += (double)g_p_iou[b];
            dmse += (double)g_p_mse[b];
            dni += (unsigned long long)g_p_ni[b];
        }
        #pragma unroll
        for (int off = 16; off > 0; off >>= 1) {
            diou += __shfl_down_sync(0xFFFFFFFFu, diou, off);
            dmse += __shfl_down_sync(0xFFFFFFFFu, dmse, off);
            dni  += __shfl_down_sync(0xFFFFFFFFu, dni, off);
        }
        __shared__ double f_iou[32];
        __shared__ double f_mse[32];
        __shared__ unsigned long long f_ni[32];
        if (lid == 0) {
            f_iou[wid] = diou;
            f_mse[wid] = dmse;
            f_ni[wid] = dni;
        }
        __syncthreads();
        if (threadIdx.x == 0) {
            double tiou = 0.0, tmse = 0.0;
            unsigned long long tni = 0ull;
            #pragma unroll
            for (int w = 0; w < NTHREADS / 32; w++) {
                tiou += f_iou[w];
                tmse += f_mse[w];
                tni += f_ni[w];
            }
            const unsigned long long tnc = (unsigned long long)n - tni;
            const double mse_denom = (double)((tni > 0ull) ? tni * 4ull : 1ull);
            const double iou_denom = (double)((tnc > 0ull) ? tnc : 1ull);
            const float mse_mean = (float)(tmse / mse_denom);
            const float iou_mean = (float)(tiou / iou_denom);
            float res_full = iou_mean + ((tni > 0ull) ? -mse_mean : 0.0f);
            out[0] = (tnc > 0ull) ? res_full : -mse_mean;
            g_ticket = 0u;  // reset for next graph replay
        }
    }
}

extern "C" void kernel_launch(void* const* d_in, const int* in_sizes, int n_in,
                              void* d_out, int out_size) {
    const float4* pr = (const float4*)d_in[0];
    const float4* gt = (const float4*)d_in[1];
    float* out = (float*)d_out;
    const int n = in_sizes[0] / 4;

    iou_dots_fused<<<NBLOCKS, NTHREADS>>>(pr, gt, out, n);
}

// round 12
// speedup vs baseline: 1.2044x; 1.1465x over previous
#include <cuda_runtime.h>
#include <cuda_bf16.h>
#include <cstdint>

#define NTHREADS 256
#define NBLOCKS 2368

// Per-block partials: every slot written each run -> no init kernel needed.
__device__ float g_p_iou[NBLOCKS];
__device__ float g_p_mse[NBLOCKS];
__device__ unsigned int g_p_ni[NBLOCKS];
// Ticket counter: statically 0; last block resets it -> graph-replay safe.
__device__ unsigned int g_ticket = 0;

// 256-bit load (Blackwell): 2 boxes per instruction, L2 256B promotion.
__device__ __forceinline__ void ldg_v8(const float* __restrict__ p, float r[8]) {
    asm volatile(
        "ld.global.nc.L2::256B.v8.f32 {%0,%1,%2,%3,%4,%5,%6,%7}, [%8];"
        : "=f"(r[0]), "=f"(r[1]), "=f"(r[2]), "=f"(r[3]),
          "=f"(r[4]), "=f"(r[5]), "=f"(r[6]), "=f"(r[7])
        : "l"(p));
}

__device__ __forceinline__ void process_box(
    float px, float py, float pz, float pw,
    float gx, float gy, float gz, float gw,
    float& iou_sum, float& mse_sum, unsigned int& n_inc)
{
    // gt corners (cx,cy,w,h -> xyxy); *0.5 is exact so FMA == mul-then-add rounding
    const float x_min_t = fmaf(gz, -0.5f, gx);
    const float x_max_t = fmaf(gz,  0.5f, gx);
    const float y_min_t = fmaf(gw, -0.5f, gy);
    const float y_max_t = fmaf(gw,  0.5f, gy);
    // pred corners clipped to [0,1]
    const float x_min_p = fmaxf(fmaf(pz, -0.5f, px), 0.0f);
    const float x_max_p = fminf(fmaf(pz,  0.5f, px), 1.0f);
    const float y_min_p = fmaxf(fmaf(pw, -0.5f, py), 0.0f);
    const float y_max_p = fminf(fmaf(pw,  0.5f, py), 1.0f);
    // overlap box
    const float o0 = fmaxf(x_min_t, x_min_p);
    const float o1 = fmaxf(y_min_t, y_min_p);
    const float o2 = fminf(x_max_t, x_max_p);
    const float o3 = fminf(y_max_t, y_max_p);

    const float wi = o2 - o0;           // sign(wi) < 0  <=>  o2 < o0 (fp-exact)
    const float hi = o3 - o1;
    const bool inc = fminf(wi, hi) < 0.0f;

    const float dx = px - gx;
    const float dy = py - gy;
    const float dz = pz - gz;
    const float dw = pw - gw;
    const float sq = fmaf(dx, dx, fmaf(dy, dy, fmaf(dz, dz, dw * dw)));

    const float inter = wi * hi;
    const float denom = pz * pw + gz * gw - inter + 1e-7f;
    const float iou = __fdividef(inter, denom);

    mse_sum += inc ? sq : 0.0f;
    iou_sum += inc ? 0.0f : iou;
    n_inc += inc ? 1u : 0u;
}

__global__ void __launch_bounds__(NTHREADS, 8) iou_dots_fused(
    const float* __restrict__ pr,
    const float* __restrict__ gt,
    float* __restrict__ out,
    int n)
{
    float iou_sum = 0.0f;
    float mse_sum = 0.0f;
    unsigned int n_inc = 0u;

    const int n_pairs = n >> 1;
    const int stride = gridDim.x * blockDim.x;
    const int tid0 = blockIdx.x * blockDim.x + threadIdx.x;

    for (int ip = tid0; ip < n_pairs; ip += stride) {
        float p[8], g[8];
        ldg_v8(pr + (size_t)ip * 8, p);   // boxes 2ip, 2ip+1 of pr
        ldg_v8(gt + (size_t)ip * 8, g);
        process_box(p[0], p[1], p[2], p[3], g[0], g[1], g[2], g[3],
                    iou_sum, mse_sum, n_inc);
        process_box(p[4], p[5], p[6], p[7], g[4], g[5], g[6], g[7],
                    iou_sum, mse_sum, n_inc);
    }
    // odd tail box (n is even for this problem, but stay correct)
    if ((n & 1) && tid0 == 0) {
        const float* pp = pr + (size_t)(n - 1) * 4;
        const float* gg = gt + (size_t)(n - 1) * 4;
        process_box(pp[0], pp[1], pp[2], pp[3], gg[0], gg[1], gg[2], gg[3],
                    iou_sum, mse_sum, n_inc);
    }

    // intra-warp reduce
    #pragma unroll
    for (int off = 16; off > 0; off >>= 1) {
        iou_sum += __shfl_down_sync(0xFFFFFFFFu, iou_sum, off);
        mse_sum += __shfl_down_sync(0xFFFFFFFFu, mse_sum, off);
        n_inc   += __shfl_down_sync(0xFFFFFFFFu, n_inc, off);
    }

    __shared__ float s_iou[8];
    __shared__ float s_mse[8];
    __shared__ unsigned int s_ni[8];
    __shared__ bool s_last;
    const int wid = threadIdx.x >> 5;
    const int lid = threadIdx.x & 31;
    if (lid == 0) {
        s_iou[wid] = iou_sum;
        s_mse[wid] = mse_sum;
        s_ni[wid] = n_inc;
    }
    __syncthreads();
    if (threadIdx.x == 0) {
        float biou = 0.0f, bmse = 0.0f;
        unsigned int bni = 0u;
        #pragma unroll
        for (int w = 0; w < NTHREADS / 32; w++) {
            biou += s_iou[w];
            bmse += s_mse[w];
            bni += s_ni[w];
        }
        g_p_iou[blockIdx.x] = biou;
        g_p_mse[blockIdx.x] = bmse;
        g_p_ni[blockIdx.x] = bni;
        __threadfence();
        const unsigned int old = atomicAdd(&g_ticket, 1u);
        s_last = (old == gridDim.x - 1u);
    }
    __syncthreads();

    if (s_last) {
        // Last block reduces all per-block partials and finalizes.
        double diou = 0.0, dmse = 0.0;
        unsigned long long dni = 0ull;
        for (int b = threadIdx.x; b < (int)gridDim.x; b += NTHREADS) {
            diou += (double)g_p_iou[b];
            dmse += (double)g_p_mse[b];
            dni += (unsigned long long)g_p_ni[b];
        }
        #pragma unroll
        for (int off = 16; off > 0; off >>= 1) {
            diou += __shfl_down_sync(0xFFFFFFFFu, diou, off);
            dmse += __shfl_down_sync(0xFFFFFFFFu, dmse, off);
            dni  += __shfl_down_sync(0xFFFFFFFFu, dni, off);
        }
        __shared__ double f_iou[8];
        __shared__ double f_mse[8];
        __shared__ unsigned long long f_ni[8];
        if (lid == 0) {
            f_iou[wid] = diou;
            f_mse[wid] = dmse;
            f_ni[wid] = dni;
        }
        __syncthreads();
        if (threadIdx.x == 0) {
            double tiou = 0.0, tmse = 0.0;
            unsigned long long tni = 0ull;
            #pragma unroll
            for (int w = 0; w < NTHREADS / 32; w++) {
                tiou += f_iou[w];
                tmse += f_mse[w];
                tni += f_ni[w];
            }
            const unsigned long long tnc = (unsigned long long)n - tni;
            const double mse_denom = (double)((tni > 0ull) ? tni * 4ull : 1ull);
            const double iou_denom = (double)((tnc > 0ull) ? tnc : 1ull);
            const float mse_mean = (float)(tmse / mse_denom);
            const float iou_mean = (float)(tiou / iou_denom);
            float res_full = iou_mean + ((tni > 0ull) ? -mse_mean : 0.0f);
            out[0] = (tnc > 0ull) ? res_full : -mse_mean;
            g_ticket = 0u;  // reset for next graph replay
        }
    }
}

extern "C" void kernel_launch(void* const* d_in, const int* in_sizes, int n_in,
                              void* d_out, int out_size) {
    const float* pr = (const float*)d_in[0];
    const float* gt = (const float*)d_in[1];
    float* out = (float*)d_out;
    const int n = in_sizes[0] / 4;

    iou_dots_fused<<<NBLOCKS, NTHREADS>>>(pr, gt, out, n);
}

// round 13
// speedup vs baseline: 1.2633x; 1.0489x over previous
#include <cuda_runtime.h>
#include <cuda_bf16.h>

#define NTHREADS 256
#define NBLOCKS 2368

// Global accumulators; statically zero. Last block resets them after use ->
// graph-replay safe. No init kernel, no per-block partial arrays.
__device__ double g_iou_d = 0.0;
__device__ double g_mse_d = 0.0;
__device__ unsigned long long g_ni_u = 0ull;
__device__ unsigned int g_ticket = 0u;

__global__ void __launch_bounds__(NTHREADS) iou_dots_fused(
    const float4* __restrict__ pr,
    const float4* __restrict__ gt,
    float* __restrict__ out,
    int n)
{
    float iou_sum = 0.0f;
    float mse_sum = 0.0f;
    unsigned int n_inc = 0u;

    // Exact R1-style main loop: plain grid-stride, float4 loads, branchy arms.
    const int stride = gridDim.x * blockDim.x;
    for (int i = blockIdx.x * blockDim.x + threadIdx.x; i < n; i += stride) {
        const float4 p = pr[i];
        const float4 g = gt[i];

        const float x_min_t = g.x - g.z * 0.5f;
        const float x_max_t = g.x + g.z * 0.5f;
        const float y_min_t = g.y - g.w * 0.5f;
        const float y_max_t = g.y + g.w * 0.5f;
        const float x_min_p = fmaxf(p.x - p.z * 0.5f, 0.0f);
        const float x_max_p = fminf(p.x + p.z * 0.5f, 1.0f);
        const float y_min_p = fmaxf(p.y - p.w * 0.5f, 0.0f);
        const float y_max_p = fminf(p.y + p.w * 0.5f, 1.0f);
        const float o0 = fmaxf(x_min_t, x_min_p);
        const float o1 = fmaxf(y_min_t, y_min_p);
        const float o2 = fminf(x_max_t, x_max_p);
        const float o3 = fminf(y_max_t, y_max_p);

        const bool incorrect = (o2 < o0) || (o3 < o1);
        if (incorrect) {
            n_inc++;
            const float dx = p.x - g.x;
            const float dy = p.y - g.y;
            const float dz = p.z - g.z;
            const float dw = p.w - g.w;
            mse_sum += dx * dx + dy * dy + dz * dz + dw * dw;
        } else {
            const float inter = (o2 - o0) * (o3 - o1);
            const float area_p = p.z * p.w;
            const float area_g = g.z * g.w;
            iou_sum += inter / (area_p + area_g - inter + 1e-7f);
        }
    }

    // intra-warp reduce
    #pragma unroll
    for (int off = 16; off > 0; off >>= 1) {
        iou_sum += __shfl_down_sync(0xFFFFFFFFu, iou_sum, off);
        mse_sum += __shfl_down_sync(0xFFFFFFFFu, mse_sum, off);
        n_inc   += __shfl_down_sync(0xFFFFFFFFu, n_inc, off);
    }

    __shared__ float s_iou[8];
    __shared__ float s_mse[8];
    __shared__ unsigned int s_ni[8];
    __shared__ bool s_last;
    const int wid = threadIdx.x >> 5;
    const int lid = threadIdx.x & 31;
    if (lid == 0) {
        s_iou[wid] = iou_sum;
        s_mse[wid] = mse_sum;
        s_ni[wid] = n_inc;
    }
    __syncthreads();
    if (threadIdx.x == 0) {
        float biou = 0.0f, bmse = 0.0f;
        unsigned int bni = 0u;
        #pragma unroll
        for (int w = 0; w < NTHREADS / 32; w++) {
            biou += s_iou[w];
            bmse += s_mse[w];
            bni += s_ni[w];
        }
        // Direct global atomics: one RED.f64 x2 + RED.u64 per block. Cheapest tail.
        atomicAdd(&g_iou_d, (double)biou);
        atomicAdd(&g_mse_d, (double)bmse);
        atomicAdd(&g_ni_u, (unsigned long long)bni);
        __threadfence();
        const unsigned int old = atomicAdd(&g_ticket, 1u);
        s_last = (old == gridDim.x - 1u);
    }
    __syncthreads();

    if (s_last && threadIdx.x == 0) {
        // All prior blocks' atomics are visible (fence before ticket + acquire via atomic).
        __threadfence();
        const double tiou = g_iou_d;
        const double tmse = g_mse_d;
        const unsigned long long tni = g_ni_u;
        const unsigned long long tnc = (unsigned long long)n - tni;
        const double mse_denom = (double)((tni > 0ull) ? tni * 4ull : 1ull);
        const double iou_denom = (double)((tnc > 0ull) ? tnc : 1ull);
        const float mse_mean = (float)(tmse / mse_denom);
        const float iou_mean = (float)(tiou / iou_denom);
        const float res_full = iou_mean + ((tni > 0ull) ? -mse_mean : 0.0f);
        out[0] = (tnc > 0ull) ? res_full : -mse_mean;
        // Reset accumulators for the next graph replay.
        g_iou_d = 0.0;
        g_mse_d = 0.0;
        g_ni_u = 0ull;
        g_ticket = 0u;
    }
}

extern "C" void kernel_launch(void* const* d_in, const int* in_sizes, int n_in,
                              void* d_out, int out_size) {
    const float4* pr = (const float4*)d_in[0];
    const float4* gt = (const float4*)d_in[1];
    float* out = (float*)d_out;
    const int n = in_sizes[0] / 4;

    iou_dots_fused<<<NBLOCKS, NTHREADS>>>(pr, gt, out, n);
}